// round 14
// baseline (speedup 1.0000x reference)
#include <cuda_runtime.h>
#include <cstdint>

#define TSEQ 4096
#define NB   4
#define BT   (TSEQ * NB)
#define CDIM 1024
#define HEAD 64
#define QT   128               // queries per attn CTA
#define NQT  (TSEQ / QT)       // 32 query tiles per batch
#define KT   64                // kv rows per tile

// Scratch (allocation-free rule: __device__ globals)
__device__ float g_Q[BT * HEAD];
__device__ float g_K[BT * HEAD];
__device__ float g_V[BT * HEAD];
// Split-KV partials: slot [ch][b][qb][row] ; ch < 4
__device__ float g_Op[4 * NB * NQT * 128 * HEAD];
__device__ float g_ml[4 * NB * NQT * 128 * 2];

__device__ __forceinline__ float tf32_rna(float x) {
    uint32_t u;
    asm("cvt.rna.tf32.f32 %0, %1;" : "=r"(u) : "f"(x));
    return __uint_as_float(u);
}
__device__ __forceinline__ uint32_t tf32_rna_u(float x) {
    uint32_t u;
    asm("cvt.rna.tf32.f32 %0, %1;" : "=r"(u) : "f"(x));
    return u;
}

// m16n8k8 tf32 mma: A row-major (4 regs), B col-major (2 regs), C fp32 (4 regs)
__device__ __forceinline__ void mma_tf32(float* c, const uint32_t* a,
                                         uint32_t b0, uint32_t b1) {
    asm volatile(
        "mma.sync.aligned.m16n8k8.row.col.f32.tf32.tf32.f32 "
        "{%0,%1,%2,%3}, {%4,%5,%6,%7}, {%8,%9}, {%0,%1,%2,%3};"
        : "+f"(c[0]), "+f"(c[1]), "+f"(c[2]), "+f"(c[3])
        : "r"(a[0]), "r"(a[1]), "r"(a[2]), "r"(a[3]), "r"(b0), "r"(b1));
}

__device__ __forceinline__ void cp16(uint32_t s, const void* g) {
    asm volatile("cp.async.cg.shared.global [%0], [%1], 16;" :: "r"(s), "l"(g));
}
#define CP_COMMIT() asm volatile("cp.async.commit_group;" ::: "memory")
#define CP_WAIT0()  asm volatile("cp.async.wait_group 0;" ::: "memory")

__device__ __forceinline__ uint32_t smem_u32(const void* p) {
    uint32_t a;
    asm("{ .reg .u64 t; cvta.to.shared.u64 t, %1; cvt.u32.u64 %0, t; }"
        : "=r"(a) : "l"(p));
    return a;
}

// ===========================================================================
// Projection, single-pass tf32 mma + cp.async double buffering, 2 CTAs/SM.
// One CTA: 64 rows x 192 cols (K|Q|V). 8 warps as 2x4; warp tile 32x48.
// ===========================================================================
#define XPITCH 36
#define WPITCH 200
#define XT_SZ (64 * XPITCH)
#define WT_SZ (32 * WPITCH)
#define X_OFF 0
#define W_OFF (2 * XT_SZ)
#define PROJ_SMEM_FLOATS (W_OFF + 2 * WT_SZ)

__global__ __launch_bounds__(256, 2) void proj_kernel(
    const float* __restrict__ x, const float* __restrict__ Wk,
    const float* __restrict__ Wq, const float* __restrict__ Wv)
{
    extern __shared__ float psm[];
    const uint32_t smb = smem_u32(psm);

    const int tid  = threadIdx.x;
    const int w    = tid >> 5;
    const int lane = tid & 31;
    const int g    = lane >> 2;
    const int tig  = lane & 3;
    const int wr   = w >> 2;      // 0..1
    const int wc   = w & 3;       // 0..3
    const int m0   = blockIdx.x * 64;

    const float* Wm[3] = {Wk, Wq, Wv};

    // prefetch chunk 0 into buffer 0
    {
        #pragma unroll
        for (int i = 0; i < 2; i++) {
            int idx = tid + i * 256;             // 512 float4 slots
            int r = idx >> 3, c4 = idx & 7;
            cp16(smb + (uint32_t)(X_OFF + r * XPITCH + c4 * 4) * 4,
                 &x[(size_t)(m0 + r) * CDIM + 0 + c4 * 4]);
        }
        #pragma unroll
        for (int m = 0; m < 3; m++) {
            #pragma unroll
            for (int i = 0; i < 2; i++) {
                int idx = tid + i * 256;         // 512 float4 slots
                int r = idx >> 4, c4 = idx & 15;
                cp16(smb + (uint32_t)(W_OFF + r * WPITCH + m * 64 + c4 * 4) * 4,
                     &Wm[m][(size_t)(0 + r) * HEAD + c4 * 4]);
            }
        }
        CP_COMMIT();
    }

    float acc[2][6][4];
    #pragma unroll
    for (int mt = 0; mt < 2; mt++)
        #pragma unroll
        for (int n = 0; n < 6; n++)
            #pragma unroll
            for (int c = 0; c < 4; c++) acc[mt][n][c] = 0.f;

    int buf = 0;
    #pragma unroll 1
    for (int k0 = 0; k0 < CDIM; k0 += 32) {
        CP_WAIT0();
        __syncthreads();

        if (k0 + 32 < CDIM) {            // prefetch next chunk into other buffer
            const int nb = buf ^ 1;
            const int kn = k0 + 32;
            #pragma unroll
            for (int i = 0; i < 2; i++) {
                int idx = tid + i * 256;
                int r = idx >> 3, c4 = idx & 7;
                cp16(smb + (uint32_t)(X_OFF + nb * XT_SZ + r * XPITCH + c4 * 4) * 4,
                     &x[(size_t)(m0 + r) * CDIM + kn + c4 * 4]);
            }
            #pragma unroll
            for (int m = 0; m < 3; m++) {
                #pragma unroll
                for (int i = 0; i < 2; i++) {
                    int idx = tid + i * 256;
                    int r = idx >> 4, c4 = idx & 15;
                    cp16(smb + (uint32_t)(W_OFF + nb * WT_SZ + r * WPITCH + m * 64 + c4 * 4) * 4,
                         &Wm[m][(size_t)(kn + r) * HEAD + c4 * 4]);
                }
            }
            CP_COMMIT();
        }

        const float* xs = psm + X_OFF + buf * XT_SZ;
        const float* ws = psm + W_OFF + buf * WT_SZ;

        #pragma unroll
        for (int ks = 0; ks < 4; ks++) {
            uint32_t a[2][4];
            #pragma unroll
            for (int mt = 0; mt < 2; mt++) {
                const int rb = 32 * wr + 16 * mt;
                a[mt][0] = tf32_rna_u(xs[(rb + g)     * XPITCH + 8 * ks + tig]);
                a[mt][1] = tf32_rna_u(xs[(rb + g + 8) * XPITCH + 8 * ks + tig]);
                a[mt][2] = tf32_rna_u(xs[(rb + g)     * XPITCH + 8 * ks + tig + 4]);
                a[mt][3] = tf32_rna_u(xs[(rb + g + 8) * XPITCH + 8 * ks + tig + 4]);
            }
            #pragma unroll
            for (int n = 0; n < 6; n++) {
                const int col = 48 * wc + 8 * n + g;
                uint32_t b0 = tf32_rna_u(ws[(8 * ks + tig)     * WPITCH + col]);
                uint32_t b1 = tf32_rna_u(ws[(8 * ks + tig + 4) * WPITCH + col]);
                mma_tf32(acc[0][n], a[0], b0, b1);
                mma_tf32(acc[1][n], a[1], b0, b1);
            }
        }
        __syncthreads();
        buf ^= 1;
    }

    // epilogue: rna-round once, store to g_K/g_Q/g_V
    float* Om[3] = {g_K, g_Q, g_V};
    #pragma unroll
    for (int n = 0; n < 6; n++) {
        const int colg = 48 * wc + 8 * n + 2 * tig;
        float* dst = Om[colg >> 6];
        const int cin = colg & 63;
        #pragma unroll
        for (int mt = 0; mt < 2; mt++) {
            const int row = m0 + 32 * wr + 16 * mt + g;
            *(float2*)&dst[(size_t)row * HEAD + cin] =
                make_float2(tf32_rna(acc[mt][n][0]), tf32_rna(acc[mt][n][1]));
            *(float2*)&dst[(size_t)(row + 8) * HEAD + cin] =
                make_float2(tf32_rna(acc[mt][n][2]), tf32_rna(acc[mt][n][3]));
        }
    }
}

// ===========================================================================
// Flash attention, mma.sync tf32, cp.async double-buffered K/V, 64-row KV
// tiles, 2 CTAs/SM. Generalized split-KV: (b,qb) has nch = qb/8+1 chunks of
// near-equal tile counts; every CTA writes unnormalized partials (O,m,l);
// reduce_kernel combines + normalizes. Grid x = 80 chunk slots, heavy first.
// ===========================================================================
#define LDK 68
#define LDV 72
#define LDP 72
#define KS_SZ (KT * LDK)
#define VS_SZ (KT * LDV)
#define KS_OFF 0
#define VS_OFF (2 * KS_SZ)
#define PS_OFF (VS_OFF + 2 * VS_SZ)
#define ATTN_SMEM_FLOATS (PS_OFF + 128 * LDP)

__global__ __launch_bounds__(256, 2) void attn_kernel()
{
    extern __shared__ float sm[];
    float* Ps = sm + PS_OFF;
    const uint32_t smb = smem_u32(sm);

    const int tid  = threadIdx.x;
    const int w    = tid >> 5;
    const int lane = tid & 31;
    const int g    = lane >> 2;
    const int tig  = lane & 3;
    const int wrow = w * 16;
    const int b    = blockIdx.y;
    const int xx   = blockIdx.x;

    // chunk slot -> (qb, ch); heavy qb first
    int qb, ch;
    if (xx < 32)      { qb = 24 + (xx >> 2); ch = xx & 3; }
    else if (xx < 56) { int t = xx - 32; qb = 16 + t / 3; ch = t % 3; }
    else if (xx < 72) { int t = xx - 56; qb = 8 + (t >> 1); ch = t & 1; }
    else              { qb = xx - 72; ch = 0; }
    const int T    = 2 * qb + 2;           // 64-row tiles in causal range
    const int nch  = (qb >> 3) + 1;
    const int cbase = T / nch, crem = T % nch;
    const int jlo  = ch * cbase + (ch < crem ? ch : crem);
    const int jhi  = jlo + cbase + (ch < crem ? 1 : 0);
    const int q0   = qb * QT;

    const int cprow = tid >> 4;            // 0..15, +i*16
    const int cpc4  = tid & 15;

    const float* Kg0 = g_K + ((size_t)(b * TSEQ)) * HEAD;
    const float* Vg0 = g_V + ((size_t)(b * TSEQ)) * HEAD;

    // prefetch tile jlo into buffer 0 (64 rows: 1024 float4 slots, 4/thread)
    {
        const float* Kg = Kg0 + (size_t)jlo * KT * HEAD;
        const float* Vg = Vg0 + (size_t)jlo * KT * HEAD;
        #pragma unroll
        for (int i = 0; i < 4; i++) {
            int idx = tid + i * 256;
            int r = idx >> 4, c4 = idx & 15;
            cp16(smb + (uint32_t)(KS_OFF + r * LDK + c4 * 4) * 4,
                 &Kg[(size_t)r * HEAD + c4 * 4]);
            cp16(smb + (uint32_t)(VS_OFF + r * LDV + c4 * 4) * 4,
                 &Vg[(size_t)r * HEAD + c4 * 4]);
        }
        (void)cprow; (void)cpc4;
        CP_COMMIT();
    }

    // Preload Q A-frags (scaled by 0.125 — exact power of 2, stays tf32)
    uint32_t aq[8][4];
    {
        const float* Qb = g_Q + ((size_t)(b * TSEQ + q0 + wrow)) * HEAD;
        #pragma unroll
        for (int k = 0; k < 8; k++) {
            aq[k][0] = __float_as_uint(0.125f * Qb[(size_t)g * HEAD + 8 * k + tig]);
            aq[k][1] = __float_as_uint(0.125f * Qb[(size_t)(g + 8) * HEAD + 8 * k + tig]);
            aq[k][2] = __float_as_uint(0.125f * Qb[(size_t)g * HEAD + 8 * k + tig + 4]);
            aq[k][3] = __float_as_uint(0.125f * Qb[(size_t)(g + 8) * HEAD + 8 * k + tig + 4]);
        }
    }

    float O[8][4];
    #pragma unroll
    for (int n = 0; n < 8; n++)
        #pragma unroll
        for (int c = 0; c < 4; c++) O[n][c] = 0.f;
    float m0r = -1e30f, m1r = -1e30f, l0 = 0.f, l1 = 0.f;
    int buf = 0;

    #pragma unroll 1
    for (int j = jlo; j < jhi; j++) {
        CP_WAIT0();
        __syncthreads();

        if (j + 1 < jhi) {
            const int nb = buf ^ 1;
            const float* Kg = Kg0 + (size_t)(j + 1) * KT * HEAD;
            const float* Vg = Vg0 + (size_t)(j + 1) * KT * HEAD;
            #pragma unroll
            for (int i = 0; i < 4; i++) {
                int idx = tid + i * 256;
                int r = idx >> 4, c4 = idx & 15;
                cp16(smb + (uint32_t)(KS_OFF + nb * KS_SZ + r * LDK + c4 * 4) * 4,
                     &Kg[(size_t)r * HEAD + c4 * 4]);
                cp16(smb + (uint32_t)(VS_OFF + nb * VS_SZ + r * LDV + c4 * 4) * 4,
                     &Vg[(size_t)r * HEAD + c4 * 4]);
            }
            CP_COMMIT();
        }

        const float* Ks = sm + KS_OFF + buf * KS_SZ;
        const float* Vs = sm + VS_OFF + buf * VS_SZ;

        // ---- S = (0.125 Q) K^T : 8 n-tiles x 8 k-steps ----
        float s[8][4];
        #pragma unroll
        for (int nt = 0; nt < 8; nt++)
            #pragma unroll
            for (int c = 0; c < 4; c++) s[nt][c] = 0.f;

        #pragma unroll
        for (int k = 0; k < 8; k++) {
            #pragma unroll
            for (int nt = 0; nt < 8; nt++) {
                uint32_t b0 = *(const uint32_t*)&Ks[(8 * nt + g) * LDK + 8 * k + tig];
                uint32_t b1 = *(const uint32_t*)&Ks[(8 * nt + g) * LDK + 8 * k + tig + 4];
                mma_tf32(s[nt], aq[k], b0, b1);
            }
        }

        // ---- mask (tiles overlapping diagonal) + row max ----
        const int r0 = wrow + g;
        const int qg0 = q0 + r0, qg1 = qg0 + 8;
        const int kv0 = j * KT;
        float mx0 = -1e30f, mx1 = -1e30f;
        const bool msk = (j >= 2 * qb);
        #pragma unroll
        for (int nt = 0; nt < 8; nt++) {
            const int c0 = kv0 + 8 * nt + 2 * tig;
            if (msk) {
                if (c0     > qg0) s[nt][0] = -1e30f;
                if (c0 + 1 > qg0) s[nt][1] = -1e30f;
                if (c0     > qg1) s[nt][2] = -1e30f;
                if (c0 + 1 > qg1) s[nt][3] = -1e30f;
            }
            mx0 = fmaxf(mx0, fmaxf(s[nt][0], s[nt][1]));
            mx1 = fmaxf(mx1, fmaxf(s[nt][2], s[nt][3]));
        }
        mx0 = fmaxf(mx0, __shfl_xor_sync(0xffffffffu, mx0, 1));
        mx0 = fmaxf(mx0, __shfl_xor_sync(0xffffffffu, mx0, 2));
        mx1 = fmaxf(mx1, __shfl_xor_sync(0xffffffffu, mx1, 1));
        mx1 = fmaxf(mx1, __shfl_xor_sync(0xffffffffu, mx1, 2));

        const float mn0 = fmaxf(m0r, mx0);
        const float mn1 = fmaxf(m1r, mx1);
        const float corr0 = __expf(m0r - mn0);
        const float corr1 = __expf(m1r - mn1);
        m0r = mn0; m1r = mn1;

        // ---- exp (rna to tf32), P -> smem, row sums ----
        float sum0 = 0.f, sum1 = 0.f;
        #pragma unroll
        for (int nt = 0; nt < 8; nt++) {
            float p0 = tf32_rna(__expf(s[nt][0] - mn0));
            float p1 = tf32_rna(__expf(s[nt][1] - mn0));
            float p2 = tf32_rna(__expf(s[nt][2] - mn1));
            float p3 = tf32_rna(__expf(s[nt][3] - mn1));
            sum0 += p0 + p1;
            sum1 += p2 + p3;
            *(float2*)&Ps[(r0)     * LDP + 8 * nt + 2 * tig] = make_float2(p0, p1);
            *(float2*)&Ps[(r0 + 8) * LDP + 8 * nt + 2 * tig] = make_float2(p2, p3);
        }
        sum0 += __shfl_xor_sync(0xffffffffu, sum0, 1);
        sum0 += __shfl_xor_sync(0xffffffffu, sum0, 2);
        sum1 += __shfl_xor_sync(0xffffffffu, sum1, 1);
        sum1 += __shfl_xor_sync(0xffffffffu, sum1, 2);
        l0 = l0 * corr0 + sum0;
        l1 = l1 * corr1 + sum1;

        #pragma unroll
        for (int n = 0; n < 8; n++) {
            O[n][0] *= corr0; O[n][1] *= corr0;
            O[n][2] *= corr1; O[n][3] *= corr1;
        }
        __syncwarp();   // own-warp P rows: sts -> lds ordering

        // ---- O += P V : 8 k-steps x 8 n-tiles ----
        #pragma unroll
        for (int k2 = 0; k2 < 8; k2++) {
            uint32_t a[4];
            a[0] = *(const uint32_t*)&Ps[(r0)     * LDP + 8 * k2 + tig];
            a[1] = *(const uint32_t*)&Ps[(r0 + 8) * LDP + 8 * k2 + tig];
            a[2] = *(const uint32_t*)&Ps[(r0)     * LDP + 8 * k2 + tig + 4];
            a[3] = *(const uint32_t*)&Ps[(r0 + 8) * LDP + 8 * k2 + tig + 4];
            #pragma unroll
            for (int nt = 0; nt < 8; nt++) {
                uint32_t b0 = *(const uint32_t*)&Vs[(8 * k2 + tig)     * LDV + 8 * nt + g];
                uint32_t b1 = *(const uint32_t*)&Vs[(8 * k2 + tig + 4) * LDV + 8 * nt + g];
                mma_tf32(O[nt], a, b0, b1);
            }
        }

        buf ^= 1;
    }

    // ---- epilogue: unnormalized partials + (m,l) ----
    const size_t pbase = (((size_t)ch * NB + b) * NQT + qb) * 128;
    float* Op0 = g_Op + (pbase + wrow + g) * HEAD;
    float* Op1 = g_Op + (pbase + wrow + g + 8) * HEAD;
    #pragma unroll
    for (int nt = 0; nt < 8; nt++) {
        *(float2*)&Op0[8 * nt + 2 * tig] = make_float2(O[nt][0], O[nt][1]);
        *(float2*)&Op1[8 * nt + 2 * tig] = make_float2(O[nt][2], O[nt][3]);
    }
    if (tig == 0) {
        *(float2*)&g_ml[(pbase + wrow + g) * 2]     = make_float2(m0r, l0);
        *(float2*)&g_ml[(pbase + wrow + g + 8) * 2] = make_float2(m1r, l1);
    }
}

// ===========================================================================
// Combine nch partials per (b,qb) (exact flash merge) + normalize.
// Grid (NQT, NB), 256 threads: thread -> (row = tid/2, 32-col chunk).
// ===========================================================================
__global__ __launch_bounds__(256, 4) void reduce_kernel(float* __restrict__ out)
{
    const int qb = blockIdx.x;
    const int b  = blockIdx.y;
    const int tid = threadIdx.x;
    const int r  = tid >> 1;
    const int cb = (tid & 1) * 32;
    const int nch = (qb >> 3) + 1;

    float mv[4], lv[4];
    float M = -1e30f;
    for (int i = 0; i < nch; i++) {
        const size_t ib = (((size_t)i * NB + b) * NQT + qb) * 128 + r;
        float2 ml = *(const float2*)&g_ml[ib * 2];
        mv[i] = ml.x; lv[i] = ml.y;
        M = fmaxf(M, ml.x);
    }
    float L = 0.f, ef[4];
    for (int i = 0; i < nch; i++) {
        ef[i] = __expf(mv[i] - M);
        L += lv[i] * ef[i];
    }
    const float inv = 1.0f / L;

    float* o = out + ((size_t)(b * TSEQ + qb * QT + r)) * HEAD;
    #pragma unroll
    for (int c = cb; c < cb + 32; c += 4) {
        float4 acc = make_float4(0.f, 0.f, 0.f, 0.f);
        for (int i = 0; i < nch; i++) {
            const size_t ib = (((size_t)i * NB + b) * NQT + qb) * 128 + r;
            float4 v = *(const float4*)&g_Op[ib * HEAD + c];
            acc.x += v.x * ef[i]; acc.y += v.y * ef[i];
            acc.z += v.z * ef[i]; acc.w += v.w * ef[i];
        }
        *(float4*)&o[c] = make_float4(acc.x * inv, acc.y * inv,
                                      acc.z * inv, acc.w * inv);
    }
}

extern "C" void kernel_launch(void* const* d_in, const int* in_sizes, int n_in,
                              void* d_out, int out_size)
{
    const float* x  = (const float*)d_in[0];
    const float* Wk = (const float*)d_in[1];
    const float* Wq = (const float*)d_in[2];
    const float* Wv = (const float*)d_in[3];
    float* out = (float*)d_out;

    cudaFuncSetAttribute(proj_kernel,
                         cudaFuncAttributeMaxDynamicSharedMemorySize,
                         PROJ_SMEM_FLOATS * (int)sizeof(float));
    cudaFuncSetAttribute(attn_kernel,
                         cudaFuncAttributeMaxDynamicSharedMemorySize,
                         ATTN_SMEM_FLOATS * (int)sizeof(float));

    proj_kernel<<<dim3(BT / 64), 256, PROJ_SMEM_FLOATS * sizeof(float)>>>(x, Wk, Wq, Wv);
    attn_kernel<<<dim3(80, NB), 256, ATTN_SMEM_FLOATS * sizeof(float)>>>();
    reduce_kernel<<<dim3(NQT, NB), 256>>>(out);
}